// round 13
// baseline (speedup 1.0000x reference)
#include <cuda_runtime.h>
#include <cuda_fp16.h>

#define M 512
#define KMAX 131072
#define K1_GRID 608    // 4 CTAs/SM
#define K2_GRID 608

__device__ __forceinline__ unsigned h2u(__half2 h) {
    unsigned u; *reinterpret_cast<__half2*>(&u) = h; return u;
}
__device__ __forceinline__ __half2 u2h(unsigned u) {
    __half2 h; *reinterpret_cast<unsigned*>(&h) = u; return h;
}

// Scratch (__device__ globals; zero-init at load; cleanup-at-end for replays)
__device__ __half   g_xh[(size_t)KMAX * M];  // fp16 shadow (written K1, read K2; ~102MB, fits L2)
__device__ float    g_v1r[4][M];   // W^T a1 replicas (atomic accum; zeroed by K1 last CTA)
__device__ float    g_v2r[4][M];   // W^T a2 replicas (zeroed by K1 last CTA)
__device__ float    g_v1[M];       // final v1 (plain store by K1 last CTA)
__device__ float    g_colsum[M];   // column sums (zeroed by K1 last CTA)
__device__ float    g_scal[4];     // [0]=c1+c2 (store), [1]=C (store), [2]=Z (zeroed)
__device__ unsigned g_cnt1, g_cnt2;

// ---------------------------------------------------------------------------
// K1 (R12 structure + shadow write): prep folded in (CTAs 0..255: W rows ->
// v replicas; CTA 256: b-dots + zero out), then ALL CTAs flat-stream x
// (__ldcs evict-first reads) for colsum, writing the fp16 shadow in the same
// flat layout. Last CTA: v1 = sum(replicas); C = c1+c2 + (colsum.v2)/K.
// ---------------------------------------------------------------------------
__global__ __launch_bounds__(256, 4) void mhi_k1(const float* __restrict__ x,
                                                 const float* __restrict__ W,
                                                 const float* __restrict__ b,
                                                 const float* __restrict__ a,
                                                 float* __restrict__ out, int K) {
    int tid  = threadIdx.x;
    int lane = tid & 31, w = tid >> 5;
    int bid  = blockIdx.x;

    // ---- prep portion (cheap; consumed only by last CTA) ----
    if (bid < 256) {
        int rg  = tid >> 7;
        int c4  = tid & 127;
        int row = bid * 2 + rg;
        float4 w4 = reinterpret_cast<const float4*>(W)[row * 128 + c4];
        float A1 = __ldg(a + row);
        float A2 = __ldg(a + M + row);
        float4 s1 = {A1*w4.x, A1*w4.y, A1*w4.z, A1*w4.w};
        float4 s2 = {A2*w4.x, A2*w4.y, A2*w4.z, A2*w4.w};
        __shared__ float4 sm1[128], sm2[128];
        if (rg == 1) { sm1[c4] = s1; sm2[c4] = s2; }
        __syncthreads();
        if (rg == 0) {
            float4 o1 = sm1[c4], o2 = sm2[c4];
            s1.x += o1.x; s1.y += o1.y; s1.z += o1.z; s1.w += o1.w;
            s2.x += o2.x; s2.y += o2.y; s2.z += o2.z; s2.w += o2.w;
            int rep = bid & 3;
            int j = c4 * 4;
            atomicAdd(&g_v1r[rep][j + 0], s1.x); atomicAdd(&g_v1r[rep][j + 1], s1.y);
            atomicAdd(&g_v1r[rep][j + 2], s1.z); atomicAdd(&g_v1r[rep][j + 3], s1.w);
            atomicAdd(&g_v2r[rep][j + 0], s2.x); atomicAdd(&g_v2r[rep][j + 1], s2.y);
            atomicAdd(&g_v2r[rep][j + 2], s2.z); atomicAdd(&g_v2r[rep][j + 3], s2.w);
        }
        __syncthreads();
    } else if (bid == 256) {
        out[tid]       = 0.f;   // d_out is poisoned: zero before K2's atomics
        out[tid + 256] = 0.f;
        float p1 = 0.f, p2 = 0.f;
        for (int i = tid; i < M; i += 256) {
            p1 += b[i] * a[i];
            p2 += b[i] * a[M + i];
        }
        #pragma unroll
        for (int o = 16; o; o >>= 1) {
            p1 += __shfl_xor_sync(0xFFFFFFFFu, p1, o);
            p2 += __shfl_xor_sync(0xFFFFFFFFu, p2, o);
        }
        __shared__ float rb[16];
        if (lane == 0) { rb[w] = p1; rb[8 + w] = p2; }
        __syncthreads();
        if (tid == 0) {
            float s = 0.f;
            #pragma unroll
            for (int q = 0; q < 16; q++) s += rb[q];
            g_scal[0] = s;      // c1 + c2
        }
    }

    // ---- flat stream: colsum + fp16 shadow write (unroll 4) ----
    __shared__ float scol[M];
    for (int j = tid; j < M; j += 256) scol[j] = 0.f;
    __syncthreads();

    const float4* X4 = reinterpret_cast<const float4*>(x);
    uint2* SH2 = reinterpret_cast<uint2*>(g_xh);    // uint2 index == float4 index
    int N4     = K * 128;
    int stride = K1_GRID * 256;     // divisible by 128
    int idx    = bid * 256 + tid;
    float4 acc = {0, 0, 0, 0};
    for (; idx + 3 * stride < N4; idx += 4 * stride) {
        float4 p0 = __ldcs(X4 + idx);
        float4 p1 = __ldcs(X4 + idx + stride);
        float4 p2 = __ldcs(X4 + idx + 2 * stride);
        float4 p3 = __ldcs(X4 + idx + 3 * stride);
        SH2[idx]              = make_uint2(h2u(__float22half2_rn({p0.x, p0.y})),
                                           h2u(__float22half2_rn({p0.z, p0.w})));
        SH2[idx + stride]     = make_uint2(h2u(__float22half2_rn({p1.x, p1.y})),
                                           h2u(__float22half2_rn({p1.z, p1.w})));
        SH2[idx + 2 * stride] = make_uint2(h2u(__float22half2_rn({p2.x, p2.y})),
                                           h2u(__float22half2_rn({p2.z, p2.w})));
        SH2[idx + 3 * stride] = make_uint2(h2u(__float22half2_rn({p3.x, p3.y})),
                                           h2u(__float22half2_rn({p3.z, p3.w})));
        acc.x += (p0.x + p1.x) + (p2.x + p3.x);
        acc.y += (p0.y + p1.y) + (p2.y + p3.y);
        acc.z += (p0.z + p1.z) + (p2.z + p3.z);
        acc.w += (p0.w + p1.w) + (p2.w + p3.w);
    }
    for (; idx < N4; idx += stride) {
        float4 p = __ldcs(X4 + idx);
        SH2[idx] = make_uint2(h2u(__float22half2_rn({p.x, p.y})),
                              h2u(__float22half2_rn({p.z, p.w})));
        acc.x += p.x; acc.y += p.y; acc.z += p.z; acc.w += p.w;
    }
    {
        int j = (tid & 127) * 4;
        atomicAdd(&scol[j + 0], acc.x); atomicAdd(&scol[j + 1], acc.y);
        atomicAdd(&scol[j + 2], acc.z); atomicAdd(&scol[j + 3], acc.w);
    }
    __syncthreads();
    for (int j = tid; j < M; j += 256) atomicAdd(&g_colsum[j], scol[j]);

    // ---- last CTA: finalize v1, compute C, cleanup for graph replay ----
    __shared__ bool isLast;
    __threadfence();
    __syncthreads();
    if (tid == 0) isLast = (atomicAdd(&g_cnt1, 1u) == gridDim.x - 1);
    __syncthreads();
    if (isLast) {
        float p = 0.f;
        for (int j = tid; j < M; j += 256) {
            float v1j = g_v1r[0][j] + g_v1r[1][j] + g_v1r[2][j] + g_v1r[3][j];
            float v2j = g_v2r[0][j] + g_v2r[1][j] + g_v2r[2][j] + g_v2r[3][j];
            g_v1[j] = v1j;
            p += g_colsum[j] * v2j;
        }
        #pragma unroll
        for (int o = 16; o; o >>= 1) p += __shfl_xor_sync(0xFFFFFFFFu, p, o);
        __shared__ float sp[8];
        if (lane == 0) sp[w] = p;
        __syncthreads();
        for (int j = tid; j < M; j += 256) {
            g_colsum[j] = 0.f;
            g_v1r[0][j] = 0.f; g_v1r[1][j] = 0.f; g_v1r[2][j] = 0.f; g_v1r[3][j] = 0.f;
            g_v2r[0][j] = 0.f; g_v2r[1][j] = 0.f; g_v2r[2][j] = 0.f; g_v2r[3][j] = 0.f;
        }
        if (tid == 0) {
            float s = 0.f;
            #pragma unroll
            for (int q = 0; q < 8; q++) s += sp[q];
            g_scal[1] = g_scal[0] + s * (1.0f / (float)K);   // C
            g_cnt1 = 0u;
        }
    }
}

// ---------------------------------------------------------------------------
// K2: reads ONLY the fp16 shadow (102MB, expected L2-resident). Warp-per-row:
// lane loads 2x uint4 (16 halves = its 16 columns), converts to fp32, dots
// with its 16 v1 values, 5-shfl reduce -> t; w = exp(relu(t + C));
// fp32 accumulate. Z per warp. Last CTA normalizes; cleanup.
// ---------------------------------------------------------------------------
__global__ __launch_bounds__(256, 4) void mhi_k2(float* __restrict__ out, int K) {
    __shared__ float scol[M];
    int tid = threadIdx.x;
    for (int j = tid; j < M; j += 256) scol[j] = 0.f;
    __syncthreads();

    float C = g_scal[1];
    int lane = tid & 31, w = tid >> 5;

    // lane owns columns [8*lane, 8*lane+8) and [256+8*lane, 256+8*lane+8)
    float va[8], vb[8];
    #pragma unroll
    for (int i = 0; i < 8; i++) {
        va[i] = __ldg(g_v1 + 8 * lane + i);
        vb[i] = __ldg(g_v1 + 256 + 8 * lane + i);
    }

    float acca[8], accb[8];
    #pragma unroll
    for (int i = 0; i < 8; i++) { acca[i] = 0.f; accb[i] = 0.f; }
    float zloc = 0.f;

    const uint4* SH = reinterpret_cast<const uint4*>(g_xh);   // 64 uint4 per row
    int gw = blockIdx.x * 8 + w;
    int nw = K2_GRID * 8;
    for (int k = gw; k < K; k += nw) {
        uint4 ua = SH[(size_t)k * 64 + lane];
        uint4 ub = SH[(size_t)k * 64 + 32 + lane];
        float fa[8], fb[8];
        {
            float2 t;
            t = __half22float2(u2h(ua.x)); fa[0] = t.x; fa[1] = t.y;
            t = __half22float2(u2h(ua.y)); fa[2] = t.x; fa[3] = t.y;
            t = __half22float2(u2h(ua.z)); fa[4] = t.x; fa[5] = t.y;
            t = __half22float2(u2h(ua.w)); fa[6] = t.x; fa[7] = t.y;
            t = __half22float2(u2h(ub.x)); fb[0] = t.x; fb[1] = t.y;
            t = __half22float2(u2h(ub.y)); fb[2] = t.x; fb[3] = t.y;
            t = __half22float2(u2h(ub.z)); fb[4] = t.x; fb[5] = t.y;
            t = __half22float2(u2h(ub.w)); fb[6] = t.x; fb[7] = t.y;
        }
        float d = 0.f;
        #pragma unroll
        for (int i = 0; i < 8; i++) d += fa[i] * va[i];
        #pragma unroll
        for (int i = 0; i < 8; i++) d += fb[i] * vb[i];
        #pragma unroll
        for (int o = 16; o; o >>= 1) d += __shfl_xor_sync(0xFFFFFFFFu, d, o);
        float wk = __expf(fmaxf(d + C, 0.f));
        #pragma unroll
        for (int i = 0; i < 8; i++) { acca[i] += wk * fa[i]; accb[i] += wk * fb[i]; }
        zloc += wk;
    }

    #pragma unroll
    for (int i = 0; i < 8; i++) {
        atomicAdd(&scol[8 * lane + i],       acca[i]);
        atomicAdd(&scol[256 + 8 * lane + i], accb[i]);
    }
    __shared__ float zw[8];
    if (lane == 0) zw[w] = zloc;   // zloc identical across lanes
    __syncthreads();
    if (tid == 0) {
        float z = 0.f;
        #pragma unroll
        for (int q = 0; q < 8; q++) z += zw[q];
        atomicAdd(&g_scal[2], z);
    }
    for (int j = tid; j < M; j += 256) atomicAdd(&out[j], scol[j]);

    // last CTA: normalize by Z; cleanup for next graph replay
    __shared__ bool isLast;
    __threadfence();
    __syncthreads();
    if (tid == 0) isLast = (atomicAdd(&g_cnt2, 1u) == gridDim.x - 1);
    __syncthreads();
    if (isLast) {
        float invZ = 1.0f / g_scal[2];
        for (int j = tid; j < M; j += 256) out[j] *= invZ;
        if (tid == 0) { g_scal[2] = 0.f; g_cnt2 = 0u; }
    }
}

// ---------------------------------------------------------------------------
extern "C" void kernel_launch(void* const* d_in, const int* in_sizes, int n_in,
                              void* d_out, int out_size) {
    const float* x = (const float*)d_in[0];   // [K, 512]
    const float* W = (const float*)d_in[1];   // [512, 512]
    const float* b = (const float*)d_in[2];   // [512]
    const float* a = (const float*)d_in[3];   // [1024]
    float* out = (float*)d_out;               // [512]
    int K = in_sizes[0] / M;

    mhi_k1<<<K1_GRID, 256>>>(x, W, b, a, out, K);
    mhi_k2<<<K2_GRID, 256>>>(out, K);
}

// round 14
// speedup vs baseline: 1.2416x; 1.2416x over previous
#include <cuda_runtime.h>

#define M 512
#define K1_GRID 592    // 4 CTAs/SM x 148 SMs -> co-residency guaranteed (barrier-safe)
#define K2_GRID 608

// Scratch (__device__ globals; zero-init at load; cleanup-at-end for replays)
__device__ float    g_q[131072 * 4]; // quarter-row dot partials (overwritten each replay)
__device__ float    g_v1r[4][M];     // W^T a1 replicas (atomic accum; zeroed by K1 last CTA)
__device__ float    g_v2r[4][M];     // W^T a2 replicas (zeroed by K1 last CTA)
__device__ float    g_colsum[M];     // column sums (used by K2! zeroed by K2 last CTA)
__device__ float    g_scal[4];       // [0]=c1+c2 (store), [1]=C (store), [2]=sum(w-1) (zeroed)
__device__ unsigned g_cA, g_relA;    // K1 start barrier (reset by K1 last CTA)
__device__ unsigned g_cnt1, g_cnt2;

// ---------------------------------------------------------------------------
// K1 (R10 structure): [prep: CTAs 0..255 -> v replicas, CTA 256 -> b-dots +
// zero out] -> grid barrier -> FLAT ascending stream of x: colsum +
// quarter-row dot partials g_q (fixed column group per thread -> v4 is ONE
// register; 32 lanes = one exact quarter row; 5-shfl butterfly, lane0 store).
// Last CTA: C = c1+c2 + (colsum.v2)/K ; cleanup (colsum KEPT for K2).
// ---------------------------------------------------------------------------
__global__ __launch_bounds__(256, 4) void mhi_k1(const float* __restrict__ x,
                                                 const float* __restrict__ W,
                                                 const float* __restrict__ b,
                                                 const float* __restrict__ a,
                                                 float* __restrict__ out, int K) {
    int tid  = threadIdx.x;
    int lane = tid & 31, w = tid >> 5;
    int bid  = blockIdx.x;

    // ---- prep portion ----
    if (bid < 256) {
        int rg  = tid >> 7;          // 0/1: which of the two W rows
        int c4w = tid & 127;         // float4 column index
        int row = bid * 2 + rg;
        float4 w4 = reinterpret_cast<const float4*>(W)[row * 128 + c4w];
        float A1 = __ldg(a + row);
        float A2 = __ldg(a + M + row);
        float4 s1 = {A1*w4.x, A1*w4.y, A1*w4.z, A1*w4.w};
        float4 s2 = {A2*w4.x, A2*w4.y, A2*w4.z, A2*w4.w};
        __shared__ float4 sm1[128], sm2[128];
        if (rg == 1) { sm1[c4w] = s1; sm2[c4w] = s2; }
        __syncthreads();
        if (rg == 0) {
            float4 o1 = sm1[c4w], o2 = sm2[c4w];
            s1.x += o1.x; s1.y += o1.y; s1.z += o1.z; s1.w += o1.w;
            s2.x += o2.x; s2.y += o2.y; s2.z += o2.z; s2.w += o2.w;
            int rep = bid & 3;
            int j = c4w * 4;
            atomicAdd(&g_v1r[rep][j + 0], s1.x); atomicAdd(&g_v1r[rep][j + 1], s1.y);
            atomicAdd(&g_v1r[rep][j + 2], s1.z); atomicAdd(&g_v1r[rep][j + 3], s1.w);
            atomicAdd(&g_v2r[rep][j + 0], s2.x); atomicAdd(&g_v2r[rep][j + 1], s2.y);
            atomicAdd(&g_v2r[rep][j + 2], s2.z); atomicAdd(&g_v2r[rep][j + 3], s2.w);
        }
    } else if (bid == 256) {
        out[tid]       = 0.f;   // d_out is poisoned: zero before K2's atomics
        out[tid + 256] = 0.f;
        float p1 = 0.f, p2 = 0.f;
        for (int i = tid; i < M; i += 256) {
            p1 += b[i] * a[i];
            p2 += b[i] * a[M + i];
        }
        #pragma unroll
        for (int o = 16; o; o >>= 1) {
            p1 += __shfl_xor_sync(0xFFFFFFFFu, p1, o);
            p2 += __shfl_xor_sync(0xFFFFFFFFu, p2, o);
        }
        __shared__ float rb[16];
        if (lane == 0) { rb[w] = p1; rb[8 + w] = p2; }
        __syncthreads();
        if (tid == 0) {
            float s = 0.f;
            #pragma unroll
            for (int q = 0; q < 16; q++) s += rb[q];
            g_scal[0] = s;      // c1 + c2
        }
    }

    // ---- grid barrier: v1 must be complete before the stream ----
    __threadfence();
    __syncthreads();
    if (tid == 0) {
        if (atomicAdd(&g_cA, 1u) == K1_GRID - 1) {
            atomicExch(&g_relA, 1u);
        } else {
            while (atomicAdd(&g_relA, 0u) == 0u) __nanosleep(64);
        }
    }
    __syncthreads();
    __threadfence();

    // ---- flat ascending stream: colsum + quarter-row dot partials ----
    __shared__ float scol[M];
    for (int j = tid; j < M; j += 256) scol[j] = 0.f;
    __syncthreads();

    int c4 = tid & 127;
    float4 v4;
    {
        const float4* r0 = reinterpret_cast<const float4*>(g_v1r[0]);
        const float4* r1 = reinterpret_cast<const float4*>(g_v1r[1]);
        const float4* r2 = reinterpret_cast<const float4*>(g_v1r[2]);
        const float4* r3 = reinterpret_cast<const float4*>(g_v1r[3]);
        float4 q0 = r0[c4], q1 = r1[c4], q2 = r2[c4], q3 = r3[c4];
        v4 = make_float4(q0.x+q1.x+q2.x+q3.x, q0.y+q1.y+q2.y+q3.y,
                         q0.z+q1.z+q2.z+q3.z, q0.w+q1.w+q2.w+q3.w);
    }

    const float4* X4 = reinterpret_cast<const float4*>(x);
    int N4     = K * 128;
    int stride = K1_GRID * 256;     // 151552, divisible by 128
    int idx    = bid * 256 + tid;
    float4 acc = {0, 0, 0, 0};
    for (; idx + 3 * stride < N4; idx += 4 * stride) {
        float4 p0 = X4[idx];
        float4 p1 = X4[idx + stride];
        float4 p2 = X4[idx + 2 * stride];
        float4 p3 = X4[idx + 3 * stride];
        float d0 = p0.x*v4.x + p0.y*v4.y + p0.z*v4.z + p0.w*v4.w;
        float d1 = p1.x*v4.x + p1.y*v4.y + p1.z*v4.z + p1.w*v4.w;
        float d2 = p2.x*v4.x + p2.y*v4.y + p2.z*v4.z + p2.w*v4.w;
        float d3 = p3.x*v4.x + p3.y*v4.y + p3.z*v4.z + p3.w*v4.w;
        #pragma unroll
        for (int o = 16; o; o >>= 1) {
            d0 += __shfl_xor_sync(0xFFFFFFFFu, d0, o);
            d1 += __shfl_xor_sync(0xFFFFFFFFu, d1, o);
            d2 += __shfl_xor_sync(0xFFFFFFFFu, d2, o);
            d3 += __shfl_xor_sync(0xFFFFFFFFu, d3, o);
        }
        if (lane == 0) {
            g_q[idx >> 5]                = d0;
            g_q[(idx + stride) >> 5]     = d1;
            g_q[(idx + 2 * stride) >> 5] = d2;
            g_q[(idx + 3 * stride) >> 5] = d3;
        }
        acc.x += (p0.x + p1.x) + (p2.x + p3.x);
        acc.y += (p0.y + p1.y) + (p2.y + p3.y);
        acc.z += (p0.z + p1.z) + (p2.z + p3.z);
        acc.w += (p0.w + p1.w) + (p2.w + p3.w);
    }
    for (; idx < N4; idx += stride) {
        float4 p = X4[idx];
        float d = p.x*v4.x + p.y*v4.y + p.z*v4.z + p.w*v4.w;
        #pragma unroll
        for (int o = 16; o; o >>= 1) d += __shfl_xor_sync(0xFFFFFFFFu, d, o);
        if (lane == 0) g_q[idx >> 5] = d;
        acc.x += p.x; acc.y += p.y; acc.z += p.z; acc.w += p.w;
    }
    {
        int j = c4 * 4;
        atomicAdd(&scol[j + 0], acc.x); atomicAdd(&scol[j + 1], acc.y);
        atomicAdd(&scol[j + 2], acc.z); atomicAdd(&scol[j + 3], acc.w);
    }
    __syncthreads();
    for (int j = tid; j < M; j += 256) atomicAdd(&g_colsum[j], scol[j]);

    // ---- last CTA: C; cleanup (KEEP g_colsum for K2) ----
    __shared__ bool isLast;
    __threadfence();
    __syncthreads();
    if (tid == 0) isLast = (atomicAdd(&g_cnt1, 1u) == gridDim.x - 1);
    __syncthreads();
    if (isLast) {
        float p = 0.f;
        for (int j = tid; j < M; j += 256) {
            float v2j = g_v2r[0][j] + g_v2r[1][j] + g_v2r[2][j] + g_v2r[3][j];
            p += g_colsum[j] * v2j;
        }
        #pragma unroll
        for (int o = 16; o; o >>= 1) p += __shfl_xor_sync(0xFFFFFFFFu, p, o);
        __shared__ float sp[8];
        if (lane == 0) sp[w] = p;
        __syncthreads();
        for (int j = tid; j < M; j += 256) {
            g_v1r[0][j] = 0.f; g_v1r[1][j] = 0.f; g_v1r[2][j] = 0.f; g_v1r[3][j] = 0.f;
            g_v2r[0][j] = 0.f; g_v2r[1][j] = 0.f; g_v2r[2][j] = 0.f; g_v2r[3][j] = 0.f;
        }
        if (tid == 0) {
            float s = 0.f;
            #pragma unroll
            for (int q = 0; q < 8; q++) s += sp[q];
            g_scal[1] = g_scal[0] + s * (1.0f / (float)K);   // C
            g_cnt1 = 0u;
            g_cA = 0u; g_relA = 0u;              // reset barrier for next replay
        }
    }
}

// ---------------------------------------------------------------------------
// K2 (ROW-SKIP, descending): out_unnorm = colsum + sum_{t+C>0} (w-1) x ;
// Z = K + sum(w-1). Rows with t+C <= 0 contribute nothing beyond colsum
// (w == 1 exactly), so ~50% of x is never read. Per 16-row batch: lanes 0-15
// load one float4 of g_q each (coalesced 256B), t = sum of quarters,
// wm1 = exp(max(t+C,0)) - 1 (exactly 0 for skipped rows), ballot, then load
// only positive rows (warp-uniform, row-coalesced). Last CTA adds colsum,
// normalizes by Z, cleans up.
// ---------------------------------------------------------------------------
__global__ __launch_bounds__(256, 4) void mhi_k2(const float* __restrict__ x,
                                                 float* __restrict__ out, int K) {
    __shared__ float scol[M];
    int tid = threadIdx.x;
    for (int j = tid; j < M; j += 256) scol[j] = 0.f;
    __syncthreads();

    float C = g_scal[1];
    int lane = tid & 31, w = tid >> 5;
    const float4* X4 = reinterpret_cast<const float4*>(x);
    const float4* Q4 = reinterpret_cast<const float4*>(g_q);

    float4 a0 = {0,0,0,0}, a1 = a0, a2 = a0, a3 = a0;
    float zloc = 0.f;
    int gw = blockIdx.x * 8 + w;
    int nw = K2_GRID * 8;
    int nbat = (K + 15) >> 4;                    // 16-row batches
    for (int bi = nbat - 1 - gw; bi >= 0; bi -= nw) {   // descending: L2-hot first
        int base = bi * 16;
        int kk = base + (lane & 15);             // lanes 16-31 duplicate (broadcast)
        float t;
        if (kk < K) {
            float4 q = __ldg(Q4 + kk);
            t = (q.x + q.y) + (q.z + q.w);
        } else {
            t = -1e30f;
        }
        float wm1 = __expf(fmaxf(t + C, 0.f)) - 1.0f;   // exactly 0 for skipped rows
        if (lane < 16) zloc += wm1;
        unsigned mask = __ballot_sync(0xFFFFFFFFu, wm1 > 0.f) & 0xFFFFu;
        while (mask) {
            int src = __ffs(mask) - 1;
            mask &= mask - 1;
            float wv = __shfl_sync(0xFFFFFFFFu, wm1, src);
            const float4* r = X4 + (size_t)(base + src) * 128;
            float4 x0 = r[lane], x1 = r[lane + 32], x2 = r[lane + 64], x3 = r[lane + 96];
            a0.x += wv*x0.x; a0.y += wv*x0.y; a0.z += wv*x0.z; a0.w += wv*x0.w;
            a1.x += wv*x1.x; a1.y += wv*x1.y; a1.z += wv*x1.z; a1.w += wv*x1.w;
            a2.x += wv*x2.x; a2.y += wv*x2.y; a2.z += wv*x2.z; a2.w += wv*x2.w;
            a3.x += wv*x3.x; a3.y += wv*x3.y; a3.z += wv*x3.z; a3.w += wv*x3.w;
        }
    }
    // reduce zloc across lanes (each lane<16 holds distinct rows' wm1)
    #pragma unroll
    for (int o = 16; o; o >>= 1) zloc += __shfl_xor_sync(0xFFFFFFFFu, zloc, o);
    __shared__ float zw[8];
    if (lane == 0) zw[w] = zloc;

    int c = 4 * lane;
    atomicAdd(&scol[c + 0],       a0.x); atomicAdd(&scol[c + 1],       a0.y);
    atomicAdd(&scol[c + 2],       a0.z); atomicAdd(&scol[c + 3],       a0.w);
    atomicAdd(&scol[128 + c + 0], a1.x); atomicAdd(&scol[128 + c + 1], a1.y);
    atomicAdd(&scol[128 + c + 2], a1.z); atomicAdd(&scol[128 + c + 3], a1.w);
    atomicAdd(&scol[256 + c + 0], a2.x); atomicAdd(&scol[256 + c + 1], a2.y);
    atomicAdd(&scol[256 + c + 2], a2.z); atomicAdd(&scol[256 + c + 3], a2.w);
    atomicAdd(&scol[384 + c + 0], a3.x); atomicAdd(&scol[384 + c + 1], a3.y);
    atomicAdd(&scol[384 + c + 2], a3.z); atomicAdd(&scol[384 + c + 3], a3.w);
    __syncthreads();
    if (tid == 0) {
        float z = 0.f;
        #pragma unroll
        for (int q = 0; q < 8; q++) z += zw[q];
        atomicAdd(&g_scal[2], z);                // sum of (w-1)
    }
    for (int j = tid; j < M; j += 256) atomicAdd(&out[j], scol[j]);

    // last CTA: out = (out + colsum) / (K + sum(w-1)); cleanup for next replay
    __shared__ bool isLast;
    __threadfence();
    __syncthreads();
    if (tid == 0) isLast = (atomicAdd(&g_cnt2, 1u) == gridDim.x - 1);
    __syncthreads();
    if (isLast) {
        float invZ = 1.0f / ((float)K + g_scal[2]);
        for (int j = tid; j < M; j += 256) {
            out[j] = (out[j] + g_colsum[j]) * invZ;
            g_colsum[j] = 0.f;                   // replay cleanup
        }
        if (tid == 0) { g_scal[2] = 0.f; g_cnt2 = 0u; }
    }
}

// ---------------------------------------------------------------------------
extern "C" void kernel_launch(void* const* d_in, const int* in_sizes, int n_in,
                              void* d_out, int out_size) {
    const float* x = (const float*)d_in[0];   // [K, 512]
    const float* W = (const float*)d_in[1];   // [512, 512]
    const float* b = (const float*)d_in[2];   // [512]
    const float* a = (const float*)d_in[3];   // [1024]
    float* out = (float*)d_out;               // [512]
    int K = in_sizes[0] / M;

    mhi_k1<<<K1_GRID, 256>>>(x, W, b, a, out, K);
    mhi_k2<<<K2_GRID, 256>>>(x, out, K);
}

// round 15
// speedup vs baseline: 1.2483x; 1.0054x over previous
#include <cuda_runtime.h>

#define M 512
#define K1_GRID 592    // 4 CTAs/SM x 148 SMs -> co-residency guaranteed (barrier-safe)
#define K2_GRID 608

// Scratch (__device__ globals; zero-init at load; cleanup-at-end for replays)
__device__ float    g_q[131072 * 4]; // quarter-row dot partials (overwritten each replay)
__device__ float    g_v1r[4][M];     // W^T a1 replicas (atomic accum; zeroed by K1 last CTA)
__device__ float    g_v2r[4][M];     // W^T a2 replicas (zeroed by K1 last CTA)
__device__ float    g_colsum[M];     // column sums (used by K2! zeroed by K2 last CTA)
__device__ float    g_scal[4];       // [0]=c1+c2 (store), [1]=C (store), [2]=sum(w-1) (zeroed)
__device__ unsigned g_cA, g_relA;    // K1 start barrier (reset by K1 last CTA)
__device__ unsigned g_cnt1, g_cnt2;
__device__ unsigned g_tick;          // K2 work-steal ticket (reset by K2 last CTA)

// ---------------------------------------------------------------------------
// K1 (unchanged from R14): [prep: CTAs 0..255 -> v replicas, CTA 256 ->
// b-dots + zero out] -> grid barrier -> FLAT ascending stream of x: colsum +
// quarter-row dot partials g_q. Last CTA: C = c1+c2 + (colsum.v2)/K ;
// cleanup (colsum KEPT for K2).
// ---------------------------------------------------------------------------
__global__ __launch_bounds__(256, 4) void mhi_k1(const float* __restrict__ x,
                                                 const float* __restrict__ W,
                                                 const float* __restrict__ b,
                                                 const float* __restrict__ a,
                                                 float* __restrict__ out, int K) {
    int tid  = threadIdx.x;
    int lane = tid & 31, w = tid >> 5;
    int bid  = blockIdx.x;

    // ---- prep portion ----
    if (bid < 256) {
        int rg  = tid >> 7;
        int c4w = tid & 127;
        int row = bid * 2 + rg;
        float4 w4 = reinterpret_cast<const float4*>(W)[row * 128 + c4w];
        float A1 = __ldg(a + row);
        float A2 = __ldg(a + M + row);
        float4 s1 = {A1*w4.x, A1*w4.y, A1*w4.z, A1*w4.w};
        float4 s2 = {A2*w4.x, A2*w4.y, A2*w4.z, A2*w4.w};
        __shared__ float4 sm1[128], sm2[128];
        if (rg == 1) { sm1[c4w] = s1; sm2[c4w] = s2; }
        __syncthreads();
        if (rg == 0) {
            float4 o1 = sm1[c4w], o2 = sm2[c4w];
            s1.x += o1.x; s1.y += o1.y; s1.z += o1.z; s1.w += o1.w;
            s2.x += o2.x; s2.y += o2.y; s2.z += o2.z; s2.w += o2.w;
            int rep = bid & 3;
            int j = c4w * 4;
            atomicAdd(&g_v1r[rep][j + 0], s1.x); atomicAdd(&g_v1r[rep][j + 1], s1.y);
            atomicAdd(&g_v1r[rep][j + 2], s1.z); atomicAdd(&g_v1r[rep][j + 3], s1.w);
            atomicAdd(&g_v2r[rep][j + 0], s2.x); atomicAdd(&g_v2r[rep][j + 1], s2.y);
            atomicAdd(&g_v2r[rep][j + 2], s2.z); atomicAdd(&g_v2r[rep][j + 3], s2.w);
        }
    } else if (bid == 256) {
        out[tid]       = 0.f;   // d_out is poisoned: zero before K2's atomics
        out[tid + 256] = 0.f;
        float p1 = 0.f, p2 = 0.f;
        for (int i = tid; i < M; i += 256) {
            p1 += b[i] * a[i];
            p2 += b[i] * a[M + i];
        }
        #pragma unroll
        for (int o = 16; o; o >>= 1) {
            p1 += __shfl_xor_sync(0xFFFFFFFFu, p1, o);
            p2 += __shfl_xor_sync(0xFFFFFFFFu, p2, o);
        }
        __shared__ float rb[16];
        if (lane == 0) { rb[w] = p1; rb[8 + w] = p2; }
        __syncthreads();
        if (tid == 0) {
            float s = 0.f;
            #pragma unroll
            for (int q = 0; q < 16; q++) s += rb[q];
            g_scal[0] = s;      // c1 + c2
        }
    }

    // ---- grid barrier ----
    __threadfence();
    __syncthreads();
    if (tid == 0) {
        if (atomicAdd(&g_cA, 1u) == K1_GRID - 1) {
            atomicExch(&g_relA, 1u);
        } else {
            while (atomicAdd(&g_relA, 0u) == 0u) __nanosleep(64);
        }
    }
    __syncthreads();
    __threadfence();

    // ---- flat ascending stream: colsum + quarter-row dot partials ----
    __shared__ float scol[M];
    for (int j = tid; j < M; j += 256) scol[j] = 0.f;
    __syncthreads();

    int c4 = tid & 127;
    float4 v4;
    {
        const float4* r0 = reinterpret_cast<const float4*>(g_v1r[0]);
        const float4* r1 = reinterpret_cast<const float4*>(g_v1r[1]);
        const float4* r2 = reinterpret_cast<const float4*>(g_v1r[2]);
        const float4* r3 = reinterpret_cast<const float4*>(g_v1r[3]);
        float4 q0 = r0[c4], q1 = r1[c4], q2 = r2[c4], q3 = r3[c4];
        v4 = make_float4(q0.x+q1.x+q2.x+q3.x, q0.y+q1.y+q2.y+q3.y,
                         q0.z+q1.z+q2.z+q3.z, q0.w+q1.w+q2.w+q3.w);
    }

    const float4* X4 = reinterpret_cast<const float4*>(x);
    int N4     = K * 128;
    int stride = K1_GRID * 256;     // divisible by 128
    int idx    = bid * 256 + tid;
    float4 acc = {0, 0, 0, 0};
    for (; idx + 3 * stride < N4; idx += 4 * stride) {
        float4 p0 = X4[idx];
        float4 p1 = X4[idx + stride];
        float4 p2 = X4[idx + 2 * stride];
        float4 p3 = X4[idx + 3 * stride];
        float d0 = p0.x*v4.x + p0.y*v4.y + p0.z*v4.z + p0.w*v4.w;
        float d1 = p1.x*v4.x + p1.y*v4.y + p1.z*v4.z + p1.w*v4.w;
        float d2 = p2.x*v4.x + p2.y*v4.y + p2.z*v4.z + p2.w*v4.w;
        float d3 = p3.x*v4.x + p3.y*v4.y + p3.z*v4.z + p3.w*v4.w;
        #pragma unroll
        for (int o = 16; o; o >>= 1) {
            d0 += __shfl_xor_sync(0xFFFFFFFFu, d0, o);
            d1 += __shfl_xor_sync(0xFFFFFFFFu, d1, o);
            d2 += __shfl_xor_sync(0xFFFFFFFFu, d2, o);
            d3 += __shfl_xor_sync(0xFFFFFFFFu, d3, o);
        }
        if (lane == 0) {
            g_q[idx >> 5]                = d0;
            g_q[(idx + stride) >> 5]     = d1;
            g_q[(idx + 2 * stride) >> 5] = d2;
            g_q[(idx + 3 * stride) >> 5] = d3;
        }
        acc.x += (p0.x + p1.x) + (p2.x + p3.x);
        acc.y += (p0.y + p1.y) + (p2.y + p3.y);
        acc.z += (p0.z + p1.z) + (p2.z + p3.z);
        acc.w += (p0.w + p1.w) + (p2.w + p3.w);
    }
    for (; idx < N4; idx += stride) {
        float4 p = X4[idx];
        float d = p.x*v4.x + p.y*v4.y + p.z*v4.z + p.w*v4.w;
        #pragma unroll
        for (int o = 16; o; o >>= 1) d += __shfl_xor_sync(0xFFFFFFFFu, d, o);
        if (lane == 0) g_q[idx >> 5] = d;
        acc.x += p.x; acc.y += p.y; acc.z += p.z; acc.w += p.w;
    }
    {
        int j = c4 * 4;
        atomicAdd(&scol[j + 0], acc.x); atomicAdd(&scol[j + 1], acc.y);
        atomicAdd(&scol[j + 2], acc.z); atomicAdd(&scol[j + 3], acc.w);
    }
    __syncthreads();
    for (int j = tid; j < M; j += 256) atomicAdd(&g_colsum[j], scol[j]);

    // ---- last CTA: C; cleanup (KEEP g_colsum for K2) ----
    __shared__ bool isLast;
    __threadfence();
    __syncthreads();
    if (tid == 0) isLast = (atomicAdd(&g_cnt1, 1u) == gridDim.x - 1);
    __syncthreads();
    if (isLast) {
        float p = 0.f;
        for (int j = tid; j < M; j += 256) {
            float v2j = g_v2r[0][j] + g_v2r[1][j] + g_v2r[2][j] + g_v2r[3][j];
            p += g_colsum[j] * v2j;
        }
        #pragma unroll
        for (int o = 16; o; o >>= 1) p += __shfl_xor_sync(0xFFFFFFFFu, p, o);
        __shared__ float sp[8];
        if (lane == 0) sp[w] = p;
        __syncthreads();
        for (int j = tid; j < M; j += 256) {
            g_v1r[0][j] = 0.f; g_v1r[1][j] = 0.f; g_v1r[2][j] = 0.f; g_v1r[3][j] = 0.f;
            g_v2r[0][j] = 0.f; g_v2r[1][j] = 0.f; g_v2r[2][j] = 0.f; g_v2r[3][j] = 0.f;
        }
        if (tid == 0) {
            float s = 0.f;
            #pragma unroll
            for (int q = 0; q < 8; q++) s += sp[q];
            g_scal[1] = g_scal[0] + s * (1.0f / (float)K);   // C
            g_cnt1 = 0u;
            g_cA = 0u; g_relA = 0u;
        }
    }
}

// ---------------------------------------------------------------------------
// K2 (ROW-SKIP v2): 32-row batches, work-stealing tickets (descending bi for
// L2-hot tail first), 2-row unroll in the mask loop (8 LDG.128 in flight).
// out_unnorm = colsum + sum_{t+C>0} (w-1) x ; Z = K + sum(w-1).
// ---------------------------------------------------------------------------
__global__ __launch_bounds__(256, 4) void mhi_k2(const float* __restrict__ x,
                                                 float* __restrict__ out, int K) {
    __shared__ float scol[M];
    int tid = threadIdx.x;
    for (int j = tid; j < M; j += 256) scol[j] = 0.f;
    __syncthreads();

    float C = g_scal[1];
    int lane = tid & 31, w = tid >> 5;
    const float4* X4 = reinterpret_cast<const float4*>(x);
    const float4* Q4 = reinterpret_cast<const float4*>(g_q);

    float4 a0 = {0,0,0,0}, a1 = a0, a2 = a0, a3 = a0;
    float zloc = 0.f;
    int nbat = (K + 31) >> 5;                    // 32-row batches

    for (;;) {
        unsigned t0 = 0;
        if (lane == 0) t0 = atomicAdd(&g_tick, 1u);
        t0 = __shfl_sync(0xFFFFFFFFu, t0, 0);
        if ((int)t0 >= nbat) break;
        int base = (nbat - 1 - (int)t0) * 32;    // descending: L2-hot tail first
        int kk = base + lane;
        float t = -1e30f;
        if (kk < K) {
            float4 q = __ldg(Q4 + kk);
            t = (q.x + q.y) + (q.z + q.w);
        }
        float wm1 = __expf(fmaxf(t + C, 0.f)) - 1.0f;   // exactly 0 for skipped rows
        zloc += wm1;                                    // each lane owns one row
        unsigned mask = __ballot_sync(0xFFFFFFFFu, wm1 > 0.f);
        while (mask) {
            int s0 = __ffs(mask) - 1;
            mask &= mask - 1;
            if (mask) {
                int s1 = __ffs(mask) - 1;
                mask &= mask - 1;
                float w0 = __shfl_sync(0xFFFFFFFFu, wm1, s0);
                float w1 = __shfl_sync(0xFFFFFFFFu, wm1, s1);
                const float4* r0 = X4 + (size_t)(base + s0) * 128;
                const float4* r1 = X4 + (size_t)(base + s1) * 128;
                float4 x0 = r0[lane], x1 = r0[lane + 32], x2 = r0[lane + 64], x3 = r0[lane + 96];
                float4 y0 = r1[lane], y1 = r1[lane + 32], y2 = r1[lane + 64], y3 = r1[lane + 96];
                a0.x += w0*x0.x + w1*y0.x; a0.y += w0*x0.y + w1*y0.y;
                a0.z += w0*x0.z + w1*y0.z; a0.w += w0*x0.w + w1*y0.w;
                a1.x += w0*x1.x + w1*y1.x; a1.y += w0*x1.y + w1*y1.y;
                a1.z += w0*x1.z + w1*y1.z; a1.w += w0*x1.w + w1*y1.w;
                a2.x += w0*x2.x + w1*y2.x; a2.y += w0*x2.y + w1*y2.y;
                a2.z += w0*x2.z + w1*y2.z; a2.w += w0*x2.w + w1*y2.w;
                a3.x += w0*x3.x + w1*y3.x; a3.y += w0*x3.y + w1*y3.y;
                a3.z += w0*x3.z + w1*y3.z; a3.w += w0*x3.w + w1*y3.w;
            } else {
                float w0 = __shfl_sync(0xFFFFFFFFu, wm1, s0);
                const float4* r0 = X4 + (size_t)(base + s0) * 128;
                float4 x0 = r0[lane], x1 = r0[lane + 32], x2 = r0[lane + 64], x3 = r0[lane + 96];
                a0.x += w0*x0.x; a0.y += w0*x0.y; a0.z += w0*x0.z; a0.w += w0*x0.w;
                a1.x += w0*x1.x; a1.y += w0*x1.y; a1.z += w0*x1.z; a1.w += w0*x1.w;
                a2.x += w0*x2.x; a2.y += w0*x2.y; a2.z += w0*x2.z; a2.w += w0*x2.w;
                a3.x += w0*x3.x; a3.y += w0*x3.y; a3.z += w0*x3.z; a3.w += w0*x3.w;
            }
        }
    }
    #pragma unroll
    for (int o = 16; o; o >>= 1) zloc += __shfl_xor_sync(0xFFFFFFFFu, zloc, o);
    __shared__ float zw[8];
    if (lane == 0) zw[w] = zloc;

    int c = 4 * lane;
    atomicAdd(&scol[c + 0],       a0.x); atomicAdd(&scol[c + 1],       a0.y);
    atomicAdd(&scol[c + 2],       a0.z); atomicAdd(&scol[c + 3],       a0.w);
    atomicAdd(&scol[128 + c + 0], a1.x); atomicAdd(&scol[128 + c + 1], a1.y);
    atomicAdd(&scol[128 + c + 2], a1.z); atomicAdd(&scol[128 + c + 3], a1.w);
    atomicAdd(&scol[256 + c + 0], a2.x); atomicAdd(&scol[256 + c + 1], a2.y);
    atomicAdd(&scol[256 + c + 2], a2.z); atomicAdd(&scol[256 + c + 3], a2.w);
    atomicAdd(&scol[384 + c + 0], a3.x); atomicAdd(&scol[384 + c + 1], a3.y);
    atomicAdd(&scol[384 + c + 2], a3.z); atomicAdd(&scol[384 + c + 3], a3.w);
    __syncthreads();
    if (tid == 0) {
        float z = 0.f;
        #pragma unroll
        for (int q = 0; q < 8; q++) z += zw[q];
        atomicAdd(&g_scal[2], z);                // sum of (w-1)
    }
    for (int j = tid; j < M; j += 256) atomicAdd(&out[j], scol[j]);

    // last CTA: out = (out + colsum) / (K + sum(w-1)); cleanup for next replay
    __shared__ bool isLast;
    __threadfence();
    __syncthreads();
    if (tid == 0) isLast = (atomicAdd(&g_cnt2, 1u) == gridDim.x - 1);
    __syncthreads();
    if (isLast) {
        float invZ = 1.0f / ((float)K + g_scal[2]);
        for (int j = tid; j < M; j += 256) {
            out[j] = (out[j] + g_colsum[j]) * invZ;
            g_colsum[j] = 0.f;
        }
        if (tid == 0) { g_scal[2] = 0.f; g_cnt2 = 0u; g_tick = 0u; }
    }
}

// ---------------------------------------------------------------------------
extern "C" void kernel_launch(void* const* d_in, const int* in_sizes, int n_in,
                              void* d_out, int out_size) {
    const float* x = (const float*)d_in[0];   // [K, 512]
    const float* W = (const float*)d_in[1];   // [512, 512]
    const float* b = (const float*)d_in[2];   // [512]
    const float* a = (const float*)d_in[3];   // [1024]
    float* out = (float*)d_out;               // [512]
    int K = in_sizes[0] / M;

    mhi_k1<<<K1_GRID, 256>>>(x, W, b, a, out, K);
    mhi_k2<<<K2_GRID, 256>>>(x, out, K);
}